// round 1
// baseline (speedup 1.0000x reference)
#include <cuda_runtime.h>
#include <cstdint>

// ---------------------------------------------------------------------------
// Windowed XCA attention, fp32. B=4, C=192, H=W=224, WS=7 -> nW=4096 windows.
//   K1: per-window QKV GEMM (576x192 @ 192x49) -> scratch
//   K2: per-window dwconv3x3 + L2-norm K/Q + KtQ softmax(n) + V*attn + proj
// ---------------------------------------------------------------------------

#define BATCH 4
#define CH    192
#define IMG   224
#define WS    7
#define HEADS 6
#define HC    32            // channels per head
#define NW    4096          // number of windows
#define OQ    576           // 3*C
#define NPIX  49
#define STR   50            // padded row stride in smem (pixels)
#define OSTR  56            // padded pixel-slot stride (8-slot groups)

typedef unsigned long long ull;

__device__ float g_qkv_scratch[(size_t)NW * OQ * NPIX];   // 462 MB scratch

__device__ __forceinline__ ull pack2(float lo, float hi) {
    ull r; asm("mov.b64 %0, {%1, %2};" : "=l"(r) : "f"(lo), "f"(hi)); return r;
}
__device__ __forceinline__ void unpack2(ull v, float& lo, float& hi) {
    asm("mov.b64 {%0, %1}, %2;" : "=f"(lo), "=f"(hi) : "l"(v));
}
__device__ __forceinline__ ull fma2(ull a, ull b, ull c) {
    ull d; asm("fma.rn.f32x2 %0, %1, %2, %3;" : "=l"(d) : "l"(a), "l"(b), "l"(c)); return d;
}

// ---------------------------------------------------------------------------
// K1: QKV GEMM per window.
// smem: x_s[192][56] (padded cols 49..55 = 0), w_s[8][580] (transposed chunk)
// block 512 threads; 504 active compute threads: ot(0..71) x pg(0..6),
// thread tile = 8 outputs x 8 pixel-slots (4 f32x2 pairs).
// ---------------------------------------------------------------------------
#define K1_SMEM_FLOATS (CH * OSTR + 8 * 580)

__global__ __launch_bounds__(512, 1)
void qkv_gemm_kernel(const float* __restrict__ x,
                     const float* __restrict__ w_qkv,
                     const float* __restrict__ b_qkv)
{
    extern __shared__ float sm1[];
    float* x_s = sm1;                 // [192][56]
    float* w_s = sm1 + CH * OSTR;     // [8][580]

    const int win = blockIdx.x;
    const int b  = win >> 10;
    const int wh = (win >> 5) & 31;
    const int ww = win & 31;
    const int t  = threadIdx.x;

    // load x window (zero padded slots)
    for (int s = t; s < CH * OSTR; s += 512) {
        const int ch = s / OSTR, m = s % OSTR;
        float v = 0.f;
        if (m < NPIX) {
            const int i = m / 7, j = m % 7;
            v = x[(((size_t)b * CH + ch) * IMG + wh * 7 + i) * IMG + ww * 7 + j];
        }
        x_s[s] = v;
    }

    const int ot = t / 7;       // 0..71 (for t<504)
    const int pg = t % 7;
    const int mb = pg * 8;

    ull acc[8][4];
#pragma unroll
    for (int i = 0; i < 8; ++i)
#pragma unroll
        for (int p = 0; p < 4; ++p) acc[i][p] = 0ULL;

    for (int kc = 0; kc < 24; ++kc) {
        __syncthreads();
        // stage transposed W chunk: w_s[cc][o] = w_qkv[o][kc*8+cc]
        for (int u = t; u < 1152; u += 512) {
            const int o = u >> 1, half = u & 1;
            const float4 wv = *(const float4*)(w_qkv + o * CH + kc * 8 + half * 4);
            const int cb = half * 4;
            w_s[(cb + 0) * 580 + o] = wv.x;
            w_s[(cb + 1) * 580 + o] = wv.y;
            w_s[(cb + 2) * 580 + o] = wv.z;
            w_s[(cb + 3) * 580 + o] = wv.w;
        }
        __syncthreads();
        if (t < 504) {
#pragma unroll
            for (int cc = 0; cc < 8; ++cc) {
                const float4 w0 = *(const float4*)&w_s[cc * 580 + ot * 8];
                const float4 w1 = *(const float4*)&w_s[cc * 580 + ot * 8 + 4];
                const float4 xa = *(const float4*)&x_s[(kc * 8 + cc) * OSTR + mb];
                const float4 xb = *(const float4*)&x_s[(kc * 8 + cc) * OSTR + mb + 4];
                ull xp[4];
                xp[0] = pack2(xa.x, xa.y); xp[1] = pack2(xa.z, xa.w);
                xp[2] = pack2(xb.x, xb.y); xp[3] = pack2(xb.z, xb.w);
                const float wv[8] = {w0.x, w0.y, w0.z, w0.w, w1.x, w1.y, w1.z, w1.w};
#pragma unroll
                for (int i = 0; i < 8; ++i) {
                    const ull wp = pack2(wv[i], wv[i]);
#pragma unroll
                    for (int p = 0; p < 4; ++p) acc[i][p] = fma2(wp, xp[p], acc[i][p]);
                }
            }
        }
    }

    if (t < 504) {
        const size_t base = (size_t)win * (OQ * NPIX);
#pragma unroll
        for (int i = 0; i < 8; ++i) {
            const int o = ot * 8 + i;
            const float bias = b_qkv[o];
#pragma unroll
            for (int p = 0; p < 4; ++p) {
                float lo, hi; unpack2(acc[i][p], lo, hi);
                const int m = mb + 2 * p;
                if (m     < NPIX) g_qkv_scratch[base + o * NPIX + m]     = lo + bias;
                if (m + 1 < NPIX) g_qkv_scratch[base + o * NPIX + m + 1] = hi + bias;
            }
        }
    }
}

// ---------------------------------------------------------------------------
// K2: dwconv + attention + proj per window. block 256 threads.
// smem: qkvd[576][50], attn[49][50](+pad, reused as proj W chunk),
//       outs[192][56], invq[6][56], invk[6][56]
// ---------------------------------------------------------------------------
#define F_QKVD (OQ * STR)      // 28800
#define F_ATTN 2456
#define F_OUTS (CH * OSTR)     // 10752
#define F_INV  (HEADS * OSTR)  // 336
#define K2_SMEM_FLOATS (F_QKVD + F_ATTN + F_OUTS + 2 * F_INV)

__global__ __launch_bounds__(256, 1)
void attn_proj_kernel(const float* __restrict__ w_dw,
                      const float* __restrict__ b_dw,
                      const float* __restrict__ w_proj,
                      const float* __restrict__ b_proj,
                      const float* __restrict__ temperature,
                      float* __restrict__ out)
{
    extern __shared__ float sm2[];
    float* qkvd = sm2;                       // [576][50]
    float* attn = sm2 + F_QKVD;              // [49][50] (+ reuse as proj wsm)
    float* outs = attn + F_ATTN;             // [192][56]
    float* invq = outs + F_OUTS;             // [6][56]
    float* invk = invq + F_INV;              // [6][56]

    const int win = blockIdx.x;
    const int b  = win >> 10;
    const int wh = (win >> 5) & 31;
    const int ww = win & 31;
    const int t  = threadIdx.x;

    const float* src0 = g_qkv_scratch + (size_t)win * (OQ * NPIX);

    // ---- phase 1: depthwise 3x3 conv (window zero-padding), per-channel ----
    for (int o = t; o < OQ; o += 256) {
        const float* src = src0 + o * NPIX;
        float in[NPIX];
#pragma unroll
        for (int p = 0; p < NPIX; ++p) in[p] = src[p];
        float w9[9];
#pragma unroll
        for (int k = 0; k < 9; ++k) w9[k] = w_dw[o * 9 + k];
        const float bb = b_dw[o];
#pragma unroll
        for (int i = 0; i < 7; ++i) {
#pragma unroll
            for (int j = 0; j < 7; ++j) {
                float s = bb;
#pragma unroll
                for (int di = -1; di <= 1; ++di) {
#pragma unroll
                    for (int dj = -1; dj <= 1; ++dj) {
                        const int ii = i + di, jj = j + dj;
                        if (ii >= 0 && ii < 7 && jj >= 0 && jj < 7)
                            s += w9[(di + 1) * 3 + (dj + 1)] * in[ii * 7 + jj];
                    }
                }
                qkvd[o * STR + i * 7 + j] = s;
            }
        }
    }
    // zero padded cols of outs (slots 49..55)
    for (int u = t; u < CH * 7; u += 256) {
        const int r = u / 7, cc = NPIX + u % 7;
        outs[r * OSTR + cc] = 0.f;
    }
    __syncthreads();

    // ---- phase 2: inverse norms (fold temperature into q side) ----
    for (int it = t; it < 2 * HEADS * NPIX; it += 256) {
        const int part = it / (HEADS * NPIX);
        const int r = it % (HEADS * NPIX);
        const int h = r / NPIX, p = r % NPIX;
        const int rb = (part * CH + h * HC) * STR;
        float s = 0.f;
#pragma unroll
        for (int c = 0; c < HC; ++c) { const float v = qkvd[rb + c * STR + p]; s += v * v; }
        const float nm = fmaxf(sqrtf(s), 1e-12f);
        if (part == 0) invq[h * OSTR + p] = temperature[h] / nm;
        else           invk[h * OSTR + p] = 1.f / nm;
    }
    __syncthreads();

    // ---- phase 3: per-head attention ----
    for (int h = 0; h < HEADS; ++h) {
        const int qb = (h * HC) * STR;
        const int kb = (CH + h * HC) * STR;
        const int vb = (2 * CH + h * HC) * STR;

        // attn[n][m] = (sum_c k[c][n] q[c][m]) * invk[n] * invq[m]
        if (t < 175) {
            const int ng = t / 7, mg = t % 7;
            const int n0 = 2 * ng, m0 = mg * 7;
            const bool hasN1 = (n0 + 1 < NPIX);
            float a0[7], a1[7];
#pragma unroll
            for (int jm = 0; jm < 7; ++jm) { a0[jm] = 0.f; a1[jm] = 0.f; }
#pragma unroll
            for (int c = 0; c < HC; ++c) {
                const float k0 = qkvd[kb + c * STR + n0];
                const float k1 = hasN1 ? qkvd[kb + c * STR + n0 + 1] : 0.f;
#pragma unroll
                for (int jm = 0; jm < 7; ++jm) {
                    const float qv = qkvd[qb + c * STR + m0 + jm];
                    a0[jm] += k0 * qv;
                    a1[jm] += k1 * qv;
                }
            }
            const float ik0 = invk[h * OSTR + n0];
#pragma unroll
            for (int jm = 0; jm < 7; ++jm)
                attn[n0 * STR + m0 + jm] = a0[jm] * ik0 * invq[h * OSTR + m0 + jm];
            if (hasN1) {
                const float ik1 = invk[h * OSTR + n0 + 1];
#pragma unroll
                for (int jm = 0; jm < 7; ++jm)
                    attn[(n0 + 1) * STR + m0 + jm] = a1[jm] * ik1 * invq[h * OSTR + m0 + jm];
            }
        }
        __syncthreads();

        // softmax over n (axis=-2) per column m
        if (t < NPIX) {
            float mx = -1e30f;
            for (int n = 0; n < NPIX; ++n) mx = fmaxf(mx, attn[n * STR + t]);
            float ssum = 0.f;
            for (int n = 0; n < NPIX; ++n) {
                const float e = __expf(attn[n * STR + t] - mx);
                attn[n * STR + t] = e;
                ssum += e;
            }
            const float r = 1.f / ssum;
            for (int n = 0; n < NPIX; ++n) attn[n * STR + t] *= r;
        }
        __syncthreads();

        // out[c][m] = sum_n v[c][n] attn[n][m]
        if (t < 112) {
            const int cg = t / 7, mg = t % 7;
            const int c0 = 2 * cg, m0 = mg * 7;
            float a0[7], a1[7];
#pragma unroll
            for (int jm = 0; jm < 7; ++jm) { a0[jm] = 0.f; a1[jm] = 0.f; }
            for (int n = 0; n < NPIX; ++n) {
                const float v0 = qkvd[vb + c0 * STR + n];
                const float v1 = qkvd[vb + (c0 + 1) * STR + n];
#pragma unroll
                for (int jm = 0; jm < 7; ++jm) {
                    const float av = attn[n * STR + m0 + jm];
                    a0[jm] += v0 * av;
                    a1[jm] += v1 * av;
                }
            }
#pragma unroll
            for (int jm = 0; jm < 7; ++jm) {
                outs[(h * HC + c0)     * OSTR + m0 + jm] = a0[jm];
                outs[(h * HC + c0 + 1) * OSTR + m0 + jm] = a1[jm];
            }
        }
        __syncthreads();
    }

    // ---- phase 4: projection GEMM (192x192 @ 192x49) in f32x2 ----
    const int og = t / 7, pg = t % 7;
    const int oc0 = og * 6, m0 = pg * 8;
    ull acc[6][4];
#pragma unroll
    for (int i = 0; i < 6; ++i)
#pragma unroll
        for (int p = 0; p < 4; ++p) acc[i][p] = 0ULL;

    float* wsm = attn;   // reuse attn area (2304 <= 2456 floats)
    for (int chk = 0; chk < 16; ++chk) {
        __syncthreads();
        for (int u = t; u < 576; u += 256) {
            const int o = u / 3, part = u % 3;
            const float4 wv = *(const float4*)(w_proj + o * CH + chk * 12 + part * 4);
            const int cb = part * 4;
            wsm[(cb + 0) * CH + o] = wv.x;
            wsm[(cb + 1) * CH + o] = wv.y;
            wsm[(cb + 2) * CH + o] = wv.z;
            wsm[(cb + 3) * CH + o] = wv.w;
        }
        __syncthreads();
        if (t < 224) {
#pragma unroll
            for (int cc = 0; cc < 12; ++cc) {
                const int c = chk * 12 + cc;
                const float4 xa = *(const float4*)&outs[c * OSTR + m0];
                const float4 xb = *(const float4*)&outs[c * OSTR + m0 + 4];
                ull xp[4];
                xp[0] = pack2(xa.x, xa.y); xp[1] = pack2(xa.z, xa.w);
                xp[2] = pack2(xb.x, xb.y); xp[3] = pack2(xb.z, xb.w);
#pragma unroll
                for (int i = 0; i < 6; ++i) {
                    const float wv = wsm[cc * CH + oc0 + i];
                    const ull wp = pack2(wv, wv);
#pragma unroll
                    for (int p = 0; p < 4; ++p) acc[i][p] = fma2(wp, xp[p], acc[i][p]);
                }
            }
        }
    }

    if (t < 224) {
#pragma unroll
        for (int i = 0; i < 6; ++i) {
            const int oc = oc0 + i;
            const float bias = b_proj[oc];
#pragma unroll
            for (int p = 0; p < 4; ++p) {
                float lo, hi; unpack2(acc[i][p], lo, hi);
                const int m = m0 + 2 * p;
                if (m < NPIX)
                    out[(((size_t)b * CH + oc) * IMG + wh * 7 + m / 7) * IMG + ww * 7 + m % 7] = lo + bias;
                if (m + 1 < NPIX) {
                    const int mm = m + 1;
                    out[(((size_t)b * CH + oc) * IMG + wh * 7 + mm / 7) * IMG + ww * 7 + mm % 7] = hi + bias;
                }
            }
        }
    }
}

// ---------------------------------------------------------------------------
extern "C" void kernel_launch(void* const* d_in, const int* in_sizes, int n_in,
                              void* d_out, int out_size)
{
    const float* x      = (const float*)d_in[0];
    const float* w_qkv  = (const float*)d_in[1];
    const float* b_qkv  = (const float*)d_in[2];
    const float* w_dw   = (const float*)d_in[3];
    const float* b_dw   = (const float*)d_in[4];
    const float* w_proj = (const float*)d_in[5];
    const float* b_proj = (const float*)d_in[6];
    const float* temp   = (const float*)d_in[7];
    float* out = (float*)d_out;

    const int smem1 = K1_SMEM_FLOATS * 4;   // 61568 B
    const int smem2 = K2_SMEM_FLOATS * 4;   // 170720 B
    cudaFuncSetAttribute(qkv_gemm_kernel,  cudaFuncAttributeMaxDynamicSharedMemorySize, smem1);
    cudaFuncSetAttribute(attn_proj_kernel, cudaFuncAttributeMaxDynamicSharedMemorySize, smem2);

    qkv_gemm_kernel<<<NW, 512, smem1>>>(x, w_qkv, b_qkv);
    attn_proj_kernel<<<NW, 256, smem2>>>(w_dw, b_dw, w_proj, b_proj, temp, out);
}

// round 2
// speedup vs baseline: 1.3698x; 1.3698x over previous
#include <cuda_runtime.h>
#include <cstdint>

// ---------------------------------------------------------------------------
// Windowed XCA attention, fp32. B=4, C=192, H=W=224, WS=7 -> nW=4096 windows.
// 4-kernel pipeline (1x1 convs commute with windowing -> dense GEMMs):
//   A: QKV dense GEMM  (576x192 @ 192x50176 per batch)  -> g_qkv (planar)
//   B: depthwise 3x3 per (window, channel)              -> g_dw  (window layout)
//   C: attention per (window, head): norms+KtQ+softmax+V -> g_attn (planar)
//   D: proj dense GEMM (192x192 @ 192x50176 per batch)  -> out   (planar)
// ---------------------------------------------------------------------------

#define BATCH 4
#define CH    192
#define IMG   224
#define HW    50176         // 224*224
#define HEADS 6
#define HC    32
#define NW    4096
#define OQ    576
#define NPIX  49
#define DWSTR 56            // g_dw row stride (16B aligned)

typedef unsigned long long ull;

__device__ float g_qkv[(size_t)BATCH * OQ * HW];     // 462 MB
__device__ float g_dw [(size_t)NW * OQ * DWSTR];     // 528 MB
__device__ float g_attn[(size_t)BATCH * CH * HW];    // 154 MB

__device__ __forceinline__ ull pack2(float lo, float hi) {
    ull r; asm("mov.b64 %0, {%1, %2};" : "=l"(r) : "f"(lo), "f"(hi)); return r;
}
__device__ __forceinline__ void unpack2(ull v, float& lo, float& hi) {
    asm("mov.b64 {%0, %1}, %2;" : "=f"(lo), "=f"(hi) : "l"(v));
}
__device__ __forceinline__ ull fma2(ull a, ull b, ull c) {
    ull d; asm("fma.rn.f32x2 %0, %1, %2, %3;" : "=l"(d) : "l"(a), "l"(b), "l"(c)); return d;
}

// ---------------------------------------------------------------------------
// A/D: 1x1 conv as dense GEMM.  out[b,o,p] = bias[o] + sum_c w[o,c]*in[b,c,p]
// Block tile 96(M) x 128(N), BK=16, 256 threads, thread tile 6x8 (f32x2).
// MODE 0: in = x param,  out = g_qkv.   MODE 1: in = g_attn, out = param.
// ---------------------------------------------------------------------------
#define BM 96
#define BN 128
#define BK 16

template<int MT, int MODE>
__global__ __launch_bounds__(256, 2)
void conv1x1_kernel(const float* __restrict__ in_p,
                    const float* __restrict__ w,
                    const float* __restrict__ bias,
                    float* __restrict__ out_p)
{
    __shared__ float a_s[BK][BM + 4];
    __shared__ float b_s[BK][BN];

    const float* in = (MODE == 0) ? in_p : (const float*)g_attn;
    float* out      = (MODE == 0) ? (float*)g_qkv : out_p;

    const int t  = threadIdx.x;
    const int n0 = blockIdx.x * BN;
    const int m0 = blockIdx.y * BM;
    const int b  = blockIdx.z;

    const float* inb = in + (size_t)b * CH * HW + n0;
    const float* wb  = w + m0 * CH;
    float* outb = out + ((size_t)b * MT + m0) * HW + n0;

    const int tx = t & 15;      // N groups (8 pixels)
    const int ty = t >> 4;      // M groups (6 outputs)
    const int pn = tx * 8;
    const int om = ty * 6;

    ull acc[6][4];
#pragma unroll
    for (int i = 0; i < 6; ++i)
#pragma unroll
        for (int p = 0; p < 4; ++p) acc[i][p] = 0ULL;

    for (int kb = 0; kb < CH; kb += BK) {
        __syncthreads();
        // stage in chunk: b_s[c][p], 512 float4
        {
            int u = t;
#pragma unroll
            for (int r = 0; r < 2; ++r, u += 256) {
                const int row = u >> 5, col = (u & 31) * 4;
                *(float4*)&b_s[row][col] =
                    *(const float4*)(inb + (size_t)(kb + row) * HW + col);
            }
        }
        // stage transposed w chunk: a_s[c][o], 384 float4
        {
            int u = t;
#pragma unroll
            for (int r = 0; r < 2; ++r, u += 256) {
                if (u < 384) {
                    const int o = u >> 2, q = (u & 3) * 4;
                    const float4 wv = *(const float4*)(wb + o * CH + kb + q);
                    a_s[q + 0][o] = wv.x;
                    a_s[q + 1][o] = wv.y;
                    a_s[q + 2][o] = wv.z;
                    a_s[q + 3][o] = wv.w;
                }
            }
        }
        __syncthreads();
#pragma unroll
        for (int kk = 0; kk < BK; ++kk) {
            float av[6];
#pragma unroll
            for (int i = 0; i < 6; ++i) av[i] = a_s[kk][om + i];
            const float4 xa = *(const float4*)&b_s[kk][pn];
            const float4 xb = *(const float4*)&b_s[kk][pn + 4];
            ull xp[4];
            xp[0] = pack2(xa.x, xa.y); xp[1] = pack2(xa.z, xa.w);
            xp[2] = pack2(xb.x, xb.y); xp[3] = pack2(xb.z, xb.w);
#pragma unroll
            for (int i = 0; i < 6; ++i) {
                const ull wp = pack2(av[i], av[i]);
#pragma unroll
                for (int p = 0; p < 4; ++p) acc[i][p] = fma2(wp, xp[p], acc[i][p]);
            }
        }
    }

#pragma unroll
    for (int i = 0; i < 6; ++i) {
        const int o = om + i;
        const float bb = bias[m0 + o];
        float r0, r1, r2, r3;
        unpack2(acc[i][0], r0, r1); unpack2(acc[i][1], r2, r3);
        *(float4*)(outb + (size_t)o * HW + pn) =
            make_float4(r0 + bb, r1 + bb, r2 + bb, r3 + bb);
        unpack2(acc[i][2], r0, r1); unpack2(acc[i][3], r2, r3);
        *(float4*)(outb + (size_t)o * HW + pn + 4) =
            make_float4(r0 + bb, r1 + bb, r2 + bb, r3 + bb);
    }
}

// ---------------------------------------------------------------------------
// B: depthwise 3x3, zero-padded per window. One thread per (window, channel).
// grid = NW*3, block = 192. Reads g_qkv planar, writes g_dw window layout.
// ---------------------------------------------------------------------------
__global__ __launch_bounds__(192)
void dwconv_kernel(const float* __restrict__ w_dw, const float* __restrict__ b_dw)
{
    const int bx  = blockIdx.x;
    const int win = bx / 3;
    const int ch  = (bx % 3) * 192 + threadIdx.x;
    const int b  = win >> 10;
    const int wh = (win >> 5) & 31;
    const int ww = win & 31;

    const float* src = g_qkv + ((size_t)b * OQ + ch) * HW + (wh * 7) * IMG + ww * 7;
    float in[NPIX];
#pragma unroll
    for (int i = 0; i < 7; ++i)
#pragma unroll
        for (int j = 0; j < 7; ++j) in[i * 7 + j] = __ldg(src + i * IMG + j);

    float w9[9];
#pragma unroll
    for (int k = 0; k < 9; ++k) w9[k] = w_dw[ch * 9 + k];
    const float bb = b_dw[ch];

    float* dst = g_dw + ((size_t)win * OQ + ch) * DWSTR;
#pragma unroll
    for (int i = 0; i < 7; ++i) {
#pragma unroll
        for (int j = 0; j < 7; ++j) {
            float s = bb;
#pragma unroll
            for (int di = -1; di <= 1; ++di) {
#pragma unroll
                for (int dj = -1; dj <= 1; ++dj) {
                    const int ii = i + di, jj = j + dj;
                    if (ii >= 0 && ii < 7 && jj >= 0 && jj < 7)
                        s += w9[(di + 1) * 3 + (dj + 1)] * in[ii * 7 + jj];
                }
            }
            dst[i * 7 + j] = s;
        }
    }
}

// ---------------------------------------------------------------------------
// C: attention per (window, head). grid (NW, HEADS), block 192, ~30 KB smem.
//   load q/k/v (32x49) -> norms -> KtQ*scales -> softmax(n) -> V*attn -> g_attn
// ---------------------------------------------------------------------------
#define CSTR 50

__global__ __launch_bounds__(192)
void attn_kernel(const float* __restrict__ temperature)
{
    __shared__ float q_s[HC * CSTR];
    __shared__ float k_s[HC * CSTR];
    __shared__ float v_s[HC * CSTR];
    __shared__ float at [NPIX * CSTR];
    __shared__ float invq[NPIX], invk[NPIX];

    const int win = blockIdx.x;
    const int h   = blockIdx.y;
    const int t   = threadIdx.x;
    const int b  = win >> 10;
    const int wh = (win >> 5) & 31;
    const int ww = win & 31;

    // load q, k, v tiles (32 channels x 49 pixels each)
    {
        const size_t wbase = (size_t)win * OQ;
#pragma unroll
        for (int sel = 0; sel < 3; ++sel) {
            float* dst = (sel == 0) ? q_s : (sel == 1) ? k_s : v_s;
            const size_t base = (wbase + sel * CH + h * HC) * DWSTR;
            for (int u = t; u < HC * NPIX; u += 192) {
                const int c = u / NPIX, p = u % NPIX;
                dst[c * CSTR + p] = g_dw[base + c * DWSTR + p];
            }
        }
    }
    __syncthreads();

    // inverse norms (temperature folded into q side)
    if (t < 2 * NPIX) {
        const int part = t / NPIX, p = t % NPIX;
        const float* s = part ? k_s : q_s;
        float acc = 0.f;
#pragma unroll
        for (int c = 0; c < HC; ++c) { const float v = s[c * CSTR + p]; acc += v * v; }
        const float nm = fmaxf(sqrtf(acc), 1e-12f);
        if (part == 0) invq[p] = temperature[h] / nm;
        else           invk[p] = 1.f / nm;
    }
    __syncthreads();

    // attn[n][m] = (sum_c k[c][n]*q[c][m]) * invk[n] * invq[m]
    if (t < 175) {
        const int n0 = 2 * (t / 7), m0 = 7 * (t % 7);
        const bool hasN1 = (n0 + 1 < NPIX);
        float a0[7], a1[7];
#pragma unroll
        for (int jm = 0; jm < 7; ++jm) { a0[jm] = 0.f; a1[jm] = 0.f; }
#pragma unroll
        for (int c = 0; c < HC; ++c) {
            const float k0 = k_s[c * CSTR + n0];
            const float k1 = hasN1 ? k_s[c * CSTR + n0 + 1] : 0.f;
#pragma unroll
            for (int jm = 0; jm < 7; ++jm) {
                const float qv = q_s[c * CSTR + m0 + jm];
                a0[jm] += k0 * qv;
                a1[jm] += k1 * qv;
            }
        }
        const float ik0 = invk[n0];
#pragma unroll
        for (int jm = 0; jm < 7; ++jm)
            at[n0 * CSTR + m0 + jm] = a0[jm] * ik0 * invq[m0 + jm];
        if (hasN1) {
            const float ik1 = invk[n0 + 1];
#pragma unroll
            for (int jm = 0; jm < 7; ++jm)
                at[(n0 + 1) * CSTR + m0 + jm] = a1[jm] * ik1 * invq[m0 + jm];
        }
    }
    __syncthreads();

    // softmax over n (axis=-2) per column m
    if (t < NPIX) {
        float mx = -1e30f;
        for (int n = 0; n < NPIX; ++n) mx = fmaxf(mx, at[n * CSTR + t]);
        float ssum = 0.f;
        for (int n = 0; n < NPIX; ++n) {
            const float e = __expf(at[n * CSTR + t] - mx);
            at[n * CSTR + t] = e;
            ssum += e;
        }
        const float r = 1.f / ssum;
        for (int n = 0; n < NPIX; ++n) at[n * CSTR + t] *= r;
    }
    __syncthreads();

    // out[c][m] = sum_n v[c][n] * attn[n][m]   -> planar g_attn
    if (t < 112) {
        const int c0 = 2 * (t / 7), mg = t % 7;     // output row i = mg
        const int m0 = 7 * mg;
        float a0[7], a1[7];
#pragma unroll
        for (int jm = 0; jm < 7; ++jm) { a0[jm] = 0.f; a1[jm] = 0.f; }
        for (int n = 0; n < NPIX; ++n) {
            const float v0 = v_s[c0 * CSTR + n];
            const float v1 = v_s[(c0 + 1) * CSTR + n];
#pragma unroll
            for (int jm = 0; jm < 7; ++jm) {
                const float av = at[n * CSTR + m0 + jm];
                a0[jm] += v0 * av;
                a1[jm] += v1 * av;
            }
        }
        float* dst = g_attn + (((size_t)(b * CH + h * HC + c0) * IMG) + wh * 7 + mg) * IMG + ww * 7;
#pragma unroll
        for (int jm = 0; jm < 7; ++jm) dst[jm] = a0[jm];
        dst += (size_t)IMG * IMG;
#pragma unroll
        for (int jm = 0; jm < 7; ++jm) dst[jm] = a1[jm];
    }
}

// ---------------------------------------------------------------------------
extern "C" void kernel_launch(void* const* d_in, const int* in_sizes, int n_in,
                              void* d_out, int out_size)
{
    const float* x      = (const float*)d_in[0];
    const float* w_qkv  = (const float*)d_in[1];
    const float* b_qkv  = (const float*)d_in[2];
    const float* w_dw   = (const float*)d_in[3];
    const float* b_dw   = (const float*)d_in[4];
    const float* w_proj = (const float*)d_in[5];
    const float* b_proj = (const float*)d_in[6];
    const float* temp   = (const float*)d_in[7];
    float* out = (float*)d_out;

    // A: QKV GEMM -> g_qkv
    conv1x1_kernel<OQ, 0><<<dim3(HW / BN, OQ / BM, BATCH), 256>>>(x, w_qkv, b_qkv, nullptr);
    // B: dwconv -> g_dw
    dwconv_kernel<<<NW * 3, 192>>>(w_dw, b_dw);
    // C: attention -> g_attn
    attn_kernel<<<dim3(NW, HEADS), 192>>>(temp);
    // D: proj GEMM -> out
    conv1x1_kernel<CH, 1><<<dim3(HW / BN, CH / BM, BATCH), 256>>>(nullptr, w_proj, b_proj, out);
}

// round 3
// speedup vs baseline: 1.4745x; 1.0764x over previous
#include <cuda_runtime.h>
#include <cstdint>

// ---------------------------------------------------------------------------
// Windowed XCA attention, fp32. B=4, C=192, H=W=224, WS=7 -> nW=4096 windows.
// 3-kernel pipeline:
//   A: QKV dense GEMM (576x192 @ 192x50176 /batch)      -> g_qkv (planar)
//   C: per (window,head): fused dwconv3x3 + norms + KtQ
//      + softmax + V*attn                               -> g_attn (planar)
//   D: proj dense GEMM (192x192 @ 192x50176 /batch)     -> out (planar)
// ---------------------------------------------------------------------------

#define BATCH 4
#define CH    192
#define IMG   224
#define HW    50176
#define HEADS 6
#define HC    32
#define NW    4096
#define OQ    576
#define NPIX  49
#define CSTR  50

typedef unsigned long long ull;

__device__ float g_qkv [(size_t)BATCH * OQ * HW];    // 462 MB
__device__ float g_attn[(size_t)BATCH * CH * HW];    // 154 MB

__device__ __forceinline__ ull pack2(float lo, float hi) {
    ull r; asm("mov.b64 %0, {%1, %2};" : "=l"(r) : "f"(lo), "f"(hi)); return r;
}
__device__ __forceinline__ void unpack2(ull v, float& lo, float& hi) {
    asm("mov.b64 {%0, %1}, %2;" : "=f"(lo), "=f"(hi) : "l"(v));
}
__device__ __forceinline__ ull fma2(ull a, ull b, ull c) {
    ull d; asm("fma.rn.f32x2 %0, %1, %2, %3;" : "=l"(d) : "l"(a), "l"(b), "l"(c)); return d;
}

// ---------------------------------------------------------------------------
// A/D: 1x1 conv as dense GEMM. out[b,o,p] = bias[o] + sum_c w[o,c]*in[b,c,p]
// Block tile 96(M) x 128(N), BK=16, 192 threads, thread tile 8x8 (f32x2),
// both smem operands read as float4 (a_s is broadcast across the warp).
// MODE 0: in = param x, out = g_qkv.  MODE 1: in = g_attn, out = param.
// ---------------------------------------------------------------------------
#define BM 96
#define BN 128
#define BK 16

template<int MT, int MODE>
__global__ __launch_bounds__(192, 2)
void conv1x1_kernel(const float* __restrict__ in_p,
                    const float* __restrict__ w,
                    const float* __restrict__ bias,
                    float* __restrict__ out_p)
{
    __shared__ float a_s[BK][BM + 4];   // [16][100] transposed weights
    __shared__ float b_s[BK][BN];       // [16][128] input pixels

    const float* in = (MODE == 0) ? in_p : (const float*)g_attn;
    float* out      = (MODE == 0) ? (float*)g_qkv : out_p;

    const int t  = threadIdx.x;
    const int n0 = blockIdx.x * BN;
    const int m0 = blockIdx.y * BM;
    const int b  = blockIdx.z;

    const float* inb = in + (size_t)b * CH * HW + n0;
    const float* wb  = w + m0 * CH;
    float* outb = out + ((size_t)b * MT + m0) * HW + n0;

    const int tx = t & 15;       // 16 N-groups of 8 pixels
    const int ty = t >> 4;       // 12 M-groups of 8 outputs
    const int pn = tx * 8;
    const int om = ty * 8;

    ull acc[8][4];
#pragma unroll
    for (int i = 0; i < 8; ++i)
#pragma unroll
        for (int p = 0; p < 4; ++p) acc[i][p] = 0ULL;

    for (int kb = 0; kb < CH; kb += BK) {
        __syncthreads();
        // stage input chunk: 512 float4
        for (int u = t; u < (BK * BN) / 4; u += 192) {
            const int row = u >> 5, col = (u & 31) * 4;
            *(float4*)&b_s[row][col] =
                *(const float4*)(inb + (size_t)(kb + row) * HW + col);
        }
        // stage transposed weight chunk: 384 float4
        for (int u = t; u < (BM * BK) / 4; u += 192) {
            const int o = u >> 2, q = (u & 3) * 4;
            const float4 wv = *(const float4*)(wb + o * CH + kb + q);
            a_s[q + 0][o] = wv.x;
            a_s[q + 1][o] = wv.y;
            a_s[q + 2][o] = wv.z;
            a_s[q + 3][o] = wv.w;
        }
        __syncthreads();
#pragma unroll
        for (int kk = 0; kk < BK; ++kk) {
            const float4 wa = *(const float4*)&a_s[kk][om];
            const float4 wc = *(const float4*)&a_s[kk][om + 4];
            const float4 xa = *(const float4*)&b_s[kk][pn];
            const float4 xb = *(const float4*)&b_s[kk][pn + 4];
            ull xp[4];
            xp[0] = pack2(xa.x, xa.y); xp[1] = pack2(xa.z, xa.w);
            xp[2] = pack2(xb.x, xb.y); xp[3] = pack2(xb.z, xb.w);
            const float av[8] = {wa.x, wa.y, wa.z, wa.w, wc.x, wc.y, wc.z, wc.w};
#pragma unroll
            for (int i = 0; i < 8; ++i) {
                const ull wp = pack2(av[i], av[i]);
#pragma unroll
                for (int p = 0; p < 4; ++p) acc[i][p] = fma2(wp, xp[p], acc[i][p]);
            }
        }
    }

#pragma unroll
    for (int i = 0; i < 8; ++i) {
        const int o = om + i;
        const float bb = bias[m0 + o];
        float r0, r1, r2, r3;
        unpack2(acc[i][0], r0, r1); unpack2(acc[i][1], r2, r3);
        *(float4*)(outb + (size_t)o * HW + pn) =
            make_float4(r0 + bb, r1 + bb, r2 + bb, r3 + bb);
        unpack2(acc[i][2], r0, r1); unpack2(acc[i][3], r2, r3);
        *(float4*)(outb + (size_t)o * HW + pn + 4) =
            make_float4(r0 + bb, r1 + bb, r2 + bb, r3 + bb);
    }
}

// ---------------------------------------------------------------------------
// C: attention per (window, head), dwconv fused.
// grid (NW, HEADS), 192 threads, ~30 KB smem.
// phase 1: 2 threads/channel (96 ch) load window from g_qkv + dwconv3x3
// phase 2: norms, phase 3: KtQ*scales, phase 4: softmax(n), phase 5: V*attn
// ---------------------------------------------------------------------------
__global__ __launch_bounds__(192)
void attn_kernel(const float* __restrict__ w_dw,
                 const float* __restrict__ b_dw,
                 const float* __restrict__ temperature)
{
    __shared__ float q_s[HC * CSTR];
    __shared__ float k_s[HC * CSTR];
    __shared__ float v_s[HC * CSTR];
    __shared__ float at [NPIX * CSTR];
    __shared__ float invq[NPIX], invk[NPIX];

    const int win = blockIdx.x;
    const int h   = blockIdx.y;
    const int t   = threadIdx.x;
    const int b  = win >> 10;
    const int wh = (win >> 5) & 31;
    const int ww = win & 31;

    // ---- phase 1: load + depthwise 3x3 (window zero-padded) ----
    {
        const int c    = t >> 1;          // 0..95
        const int half = t & 1;
        const int sel  = c >> 5;          // 0=q 1=k 2=v
        const int cc   = c & 31;
        const int ch   = sel * CH + h * HC + cc;
        const float* src = g_qkv + (size_t)(b * OQ + ch) * HW + (wh * 7) * IMG + ww * 7;
        float* dstp = (sel == 0) ? q_s : (sel == 1) ? k_s : v_s;

        float w9[9];
#pragma unroll
        for (int k = 0; k < 9; ++k) w9[k] = w_dw[ch * 9 + k];
        const float bb = b_dw[ch];

        if (!half) {
            // output rows 0..3, input rows 0..4
            float in[5][7];
#pragma unroll
            for (int r = 0; r < 5; ++r)
#pragma unroll
                for (int j = 0; j < 7; ++j) in[r][j] = __ldg(src + r * IMG + j);
#pragma unroll
            for (int i = 0; i < 4; ++i) {
#pragma unroll
                for (int j = 0; j < 7; ++j) {
                    float s = bb;
#pragma unroll
                    for (int di = -1; di <= 1; ++di) {
                        const int ii = i + di;
                        if (ii < 0) continue;
#pragma unroll
                        for (int dj = -1; dj <= 1; ++dj) {
                            const int jj = j + dj;
                            if (jj >= 0 && jj < 7)
                                s += w9[(di + 1) * 3 + (dj + 1)] * in[ii][jj];
                        }
                    }
                    dstp[cc * CSTR + i * 7 + j] = s;
                }
            }
        } else {
            // output rows 4..6, input rows 3..6
            float in[4][7];
#pragma unroll
            for (int r = 0; r < 4; ++r)
#pragma unroll
                for (int j = 0; j < 7; ++j) in[r][j] = __ldg(src + (3 + r) * IMG + j);
#pragma unroll
            for (int i = 4; i < 7; ++i) {
#pragma unroll
                for (int j = 0; j < 7; ++j) {
                    float s = bb;
#pragma unroll
                    for (int di = -1; di <= 1; ++di) {
                        const int ii = i + di;
                        if (ii > 6) continue;
#pragma unroll
                        for (int dj = -1; dj <= 1; ++dj) {
                            const int jj = j + dj;
                            if (jj >= 0 && jj < 7)
                                s += w9[(di + 1) * 3 + (dj + 1)] * in[ii - 3][jj];
                        }
                    }
                    dstp[cc * CSTR + i * 7 + j] = s;
                }
            }
        }
    }
    __syncthreads();

    // ---- phase 2: inverse norms (temperature folded into q side) ----
    if (t < 2 * NPIX) {
        const int part = t / NPIX, p = t % NPIX;
        const float* s = part ? k_s : q_s;
        float acc = 0.f;
#pragma unroll
        for (int c = 0; c < HC; ++c) { const float v = s[c * CSTR + p]; acc += v * v; }
        const float nm = fmaxf(sqrtf(acc), 1e-12f);
        if (part == 0) invq[p] = temperature[h] / nm;
        else           invk[p] = 1.f / nm;
    }
    __syncthreads();

    // ---- phase 3: attn[n][m] = (sum_c k[c][n]*q[c][m]) * invk[n]*invq[m] ----
    if (t < 175) {
        const int n0 = 2 * (t / 7), m0 = 7 * (t % 7);
        const bool hasN1 = (n0 + 1 < NPIX);
        float a0[7], a1[7];
#pragma unroll
        for (int jm = 0; jm < 7; ++jm) { a0[jm] = 0.f; a1[jm] = 0.f; }
#pragma unroll
        for (int c = 0; c < HC; ++c) {
            const float k0 = k_s[c * CSTR + n0];
            const float k1 = hasN1 ? k_s[c * CSTR + n0 + 1] : 0.f;
#pragma unroll
            for (int jm = 0; jm < 7; ++jm) {
                const float qv = q_s[c * CSTR + m0 + jm];
                a0[jm] += k0 * qv;
                a1[jm] += k1 * qv;
            }
        }
        const float ik0 = invk[n0];
#pragma unroll
        for (int jm = 0; jm < 7; ++jm)
            at[n0 * CSTR + m0 + jm] = a0[jm] * ik0 * invq[m0 + jm];
        if (hasN1) {
            const float ik1 = invk[n0 + 1];
#pragma unroll
            for (int jm = 0; jm < 7; ++jm)
                at[(n0 + 1) * CSTR + m0 + jm] = a1[jm] * ik1 * invq[m0 + jm];
        }
    }
    __syncthreads();

    // ---- phase 4: softmax over n per column m ----
    if (t < NPIX) {
        float mx = -1e30f;
        for (int n = 0; n < NPIX; ++n) mx = fmaxf(mx, at[n * CSTR + t]);
        float ssum = 0.f;
        for (int n = 0; n < NPIX; ++n) {
            const float e = __expf(at[n * CSTR + t] - mx);
            at[n * CSTR + t] = e;
            ssum += e;
        }
        const float r = 1.f / ssum;
        for (int n = 0; n < NPIX; ++n) at[n * CSTR + t] *= r;
    }
    __syncthreads();

    // ---- phase 5: out[c][m] = sum_n v[c][n]*attn[n][m] -> planar g_attn ----
    if (t < 112) {
        const int c0 = 2 * (t / 7), mg = t % 7;
        const int m0 = 7 * mg;
        float a0[7], a1[7];
#pragma unroll
        for (int jm = 0; jm < 7; ++jm) { a0[jm] = 0.f; a1[jm] = 0.f; }
        for (int n = 0; n < NPIX; ++n) {
            const float v0 = v_s[c0 * CSTR + n];
            const float v1 = v_s[(c0 + 1) * CSTR + n];
#pragma unroll
            for (int jm = 0; jm < 7; ++jm) {
                const float av = at[n * CSTR + m0 + jm];
                a0[jm] += v0 * av;
                a1[jm] += v1 * av;
            }
        }
        float* dst = g_attn + (((size_t)(b * CH + h * HC + c0) * IMG) + wh * 7 + mg) * IMG + ww * 7;
#pragma unroll
        for (int jm = 0; jm < 7; ++jm) dst[jm] = a0[jm];
        dst += (size_t)IMG * IMG;
#pragma unroll
        for (int jm = 0; jm < 7; ++jm) dst[jm] = a1[jm];
    }
}

// ---------------------------------------------------------------------------
extern "C" void kernel_launch(void* const* d_in, const int* in_sizes, int n_in,
                              void* d_out, int out_size)
{
    const float* x      = (const float*)d_in[0];
    const float* w_qkv  = (const float*)d_in[1];
    const float* b_qkv  = (const float*)d_in[2];
    const float* w_dw   = (const float*)d_in[3];
    const float* b_dw   = (const float*)d_in[4];
    const float* w_proj = (const float*)d_in[5];
    const float* b_proj = (const float*)d_in[6];
    const float* temp   = (const float*)d_in[7];
    float* out = (float*)d_out;

    // A: QKV GEMM -> g_qkv
    conv1x1_kernel<OQ, 0><<<dim3(HW / BN, OQ / BM, BATCH), 192>>>(x, w_qkv, b_qkv, nullptr);
    // C: fused dwconv + attention -> g_attn
    attn_kernel<<<dim3(NW, HEADS), 192>>>(w_dw, b_dw, temp);
    // D: proj GEMM -> out
    conv1x1_kernel<CH, 1><<<dim3(HW / BN, CH / BM, BATCH), 192>>>(nullptr, w_proj, b_proj, out);
}

// round 4
// speedup vs baseline: 1.6752x; 1.1361x over previous
#include <cuda_runtime.h>
#include <cstdint>

// ---------------------------------------------------------------------------
// Windowed XCA attention, fp32. B=4, C=192, H=W=224, WS=7 -> nW=4096 windows.
// 3-kernel pipeline:
//   A: QKV dense GEMM (576x192 @ 192x50176 /batch)  -> g_qkv (planar)  [dbuf]
//   C: per (window,head): fused dwconv3x3 + norms + KtQ + softmax + V*attn
//   D: proj dense GEMM (192x192 @ 192x50176 /batch) -> out (planar)    [dbuf]
// ---------------------------------------------------------------------------

#define BATCH 4
#define CH    192
#define IMG   224
#define HW    50176
#define HEADS 6
#define HC    32
#define NW    4096
#define OQ    576
#define NPIX  49
#define CSTR  50

typedef unsigned long long ull;

__device__ float g_qkv [(size_t)BATCH * OQ * HW];    // 462 MB
__device__ float g_attn[(size_t)BATCH * CH * HW];    // 154 MB

__device__ __forceinline__ ull pack2(float lo, float hi) {
    ull r; asm("mov.b64 %0, {%1, %2};" : "=l"(r) : "f"(lo), "f"(hi)); return r;
}
__device__ __forceinline__ void unpack2(ull v, float& lo, float& hi) {
    asm("mov.b64 {%0, %1}, %2;" : "=f"(lo), "=f"(hi) : "l"(v));
}
__device__ __forceinline__ ull fma2(ull a, ull b, ull c) {
    ull d; asm("fma.rn.f32x2 %0, %1, %2, %3;" : "=l"(d) : "l"(a), "l"(b), "l"(c)); return d;
}

// ---------------------------------------------------------------------------
// A/D: 1x1 conv dense GEMM, double-buffered smem + register prefetch.
// Block tile 96(M) x 128(N), BK=16, 192 threads, thread tile 8x8 (f32x2).
// MODE 0: in = param x, out = g_qkv.  MODE 1: in = g_attn, out = param.
// ---------------------------------------------------------------------------
#define BM 96
#define BN 128
#define BK 16
#define KITERS (CH / BK)   // 12

template<int MT, int MODE>
__global__ __launch_bounds__(192, 2)
void conv1x1_kernel(const float* __restrict__ in_p,
                    const float* __restrict__ w,
                    const float* __restrict__ bias,
                    float* __restrict__ out_p)
{
    __shared__ float a_s[2][BK][BM + 4];   // transposed weights
    __shared__ float b_s[2][BK][BN];       // input pixels

    const float* in = (MODE == 0) ? in_p : (const float*)g_attn;
    float* out      = (MODE == 0) ? (float*)g_qkv : out_p;

    const int t  = threadIdx.x;
    const int n0 = blockIdx.x * BN;
    const int m0 = blockIdx.y * BM;
    const int b  = blockIdx.z;

    const float* inb = in + (size_t)b * CH * HW + n0;
    const float* wb  = w + m0 * CH;
    float* outb = out + ((size_t)b * MT + m0) * HW + n0;

    const int tx = t & 15;       // 16 N-groups of 8 pixels
    const int ty = t >> 4;       // 12 M-groups of 8 outputs
    const int pn = tx * 8;
    const int om = ty * 8;

    // prefetch mapping
    const int bu0 = t, bu1 = t + 192, bu2 = t + 384;       // b tile: 512 float4
    const int au0 = t, au1 = t + 192;                      // a tile: 384 float4
    const int b_row0 = bu0 >> 5, b_col0 = (bu0 & 31) * 4;
    const int b_row1 = bu1 >> 5, b_col1 = (bu1 & 31) * 4;
    const int b_row2 = bu2 >> 5, b_col2 = (bu2 & 31) * 4;
    const int a_o0 = au0 >> 2, a_q0 = (au0 & 3) * 4;
    const int a_o1 = au1 >> 2, a_q1 = (au1 & 3) * 4;

    float4 pb0, pb1, pb2, pa0, pa1;

    // prologue: load tile 0
    {
        const int kb = 0;
        pb0 = *(const float4*)(inb + (size_t)(kb + b_row0) * HW + b_col0);
        pb1 = *(const float4*)(inb + (size_t)(kb + b_row1) * HW + b_col1);
        if (t < 128) pb2 = *(const float4*)(inb + (size_t)(kb + b_row2) * HW + b_col2);
        pa0 = *(const float4*)(wb + a_o0 * CH + kb + a_q0);
        pa1 = *(const float4*)(wb + a_o1 * CH + kb + a_q1);
        *(float4*)&b_s[0][b_row0][b_col0] = pb0;
        *(float4*)&b_s[0][b_row1][b_col1] = pb1;
        if (t < 128) *(float4*)&b_s[0][b_row2][b_col2] = pb2;
        a_s[0][a_q0 + 0][a_o0] = pa0.x; a_s[0][a_q0 + 1][a_o0] = pa0.y;
        a_s[0][a_q0 + 2][a_o0] = pa0.z; a_s[0][a_q0 + 3][a_o0] = pa0.w;
        a_s[0][a_q1 + 0][a_o1] = pa1.x; a_s[0][a_q1 + 1][a_o1] = pa1.y;
        a_s[0][a_q1 + 2][a_o1] = pa1.z; a_s[0][a_q1 + 3][a_o1] = pa1.w;
    }
    __syncthreads();

    ull acc[8][4];
#pragma unroll
    for (int i = 0; i < 8; ++i)
#pragma unroll
        for (int p = 0; p < 4; ++p) acc[i][p] = 0ULL;

    for (int it = 0; it < KITERS; ++it) {
        const int cur = it & 1;
        // issue global loads for next tile (latency hidden under compute)
        if (it < KITERS - 1) {
            const int kb = (it + 1) * BK;
            pb0 = *(const float4*)(inb + (size_t)(kb + b_row0) * HW + b_col0);
            pb1 = *(const float4*)(inb + (size_t)(kb + b_row1) * HW + b_col1);
            if (t < 128) pb2 = *(const float4*)(inb + (size_t)(kb + b_row2) * HW + b_col2);
            pa0 = *(const float4*)(wb + a_o0 * CH + kb + a_q0);
            pa1 = *(const float4*)(wb + a_o1 * CH + kb + a_q1);
        }
        // compute current tile
#pragma unroll
        for (int kk = 0; kk < BK; ++kk) {
            const float4 wa = *(const float4*)&a_s[cur][kk][om];
            const float4 wc = *(const float4*)&a_s[cur][kk][om + 4];
            const float4 xa = *(const float4*)&b_s[cur][kk][pn];
            const float4 xb = *(const float4*)&b_s[cur][kk][pn + 4];
            ull xp[4];
            xp[0] = pack2(xa.x, xa.y); xp[1] = pack2(xa.z, xa.w);
            xp[2] = pack2(xb.x, xb.y); xp[3] = pack2(xb.z, xb.w);
            const float av[8] = {wa.x, wa.y, wa.z, wa.w, wc.x, wc.y, wc.z, wc.w};
#pragma unroll
            for (int i = 0; i < 8; ++i) {
                const ull wp = pack2(av[i], av[i]);
#pragma unroll
                for (int p = 0; p < 4; ++p) acc[i][p] = fma2(wp, xp[p], acc[i][p]);
            }
        }
        // store prefetched tile to the other buffer
        if (it < KITERS - 1) {
            const int nb = cur ^ 1;
            *(float4*)&b_s[nb][b_row0][b_col0] = pb0;
            *(float4*)&b_s[nb][b_row1][b_col1] = pb1;
            if (t < 128) *(float4*)&b_s[nb][b_row2][b_col2] = pb2;
            a_s[nb][a_q0 + 0][a_o0] = pa0.x; a_s[nb][a_q0 + 1][a_o0] = pa0.y;
            a_s[nb][a_q0 + 2][a_o0] = pa0.z; a_s[nb][a_q0 + 3][a_o0] = pa0.w;
            a_s[nb][a_q1 + 0][a_o1] = pa1.x; a_s[nb][a_q1 + 1][a_o1] = pa1.y;
            a_s[nb][a_q1 + 2][a_o1] = pa1.z; a_s[nb][a_q1 + 3][a_o1] = pa1.w;
            __syncthreads();
        }
    }

#pragma unroll
    for (int i = 0; i < 8; ++i) {
        const int o = om + i;
        const float bb = bias[m0 + o];
        float r0, r1, r2, r3;
        unpack2(acc[i][0], r0, r1); unpack2(acc[i][1], r2, r3);
        *(float4*)(outb + (size_t)o * HW + pn) =
            make_float4(r0 + bb, r1 + bb, r2 + bb, r3 + bb);
        unpack2(acc[i][2], r0, r1); unpack2(acc[i][3], r2, r3);
        *(float4*)(outb + (size_t)o * HW + pn + 4) =
            make_float4(r0 + bb, r1 + bb, r2 + bb, r3 + bb);
    }
}

// ---------------------------------------------------------------------------
// C: attention per (window, head), dwconv fused. grid (NW, HEADS), 192 thr.
// ---------------------------------------------------------------------------
__global__ __launch_bounds__(192)
void attn_kernel(const float* __restrict__ w_dw,
                 const float* __restrict__ b_dw,
                 const float* __restrict__ temperature)
{
    __shared__ float q_s[HC * CSTR];
    __shared__ float k_s[HC * CSTR];
    __shared__ float v_s[HC * CSTR];
    __shared__ float at [NPIX * CSTR];
    __shared__ float invq[NPIX], invk[NPIX];

    const int win = blockIdx.x;
    const int h   = blockIdx.y;
    const int t   = threadIdx.x;
    const int b  = win >> 10;
    const int wh = (win >> 5) & 31;
    const int ww = win & 31;

    // ---- phase 1: load + depthwise 3x3 (window zero-padded) ----
    {
        const int c    = t >> 1;          // 0..95
        const int half = t & 1;
        const int sel  = c >> 5;          // 0=q 1=k 2=v
        const int cc   = c & 31;
        const int ch   = sel * CH + h * HC + cc;
        const float* src = g_qkv + (size_t)(b * OQ + ch) * HW + (wh * 7) * IMG + ww * 7;
        float* dstp = (sel == 0) ? q_s : (sel == 1) ? k_s : v_s;

        float w9[9];
#pragma unroll
        for (int k = 0; k < 9; ++k) w9[k] = w_dw[ch * 9 + k];
        const float bb = b_dw[ch];

        if (!half) {
            float in[5][7];
#pragma unroll
            for (int r = 0; r < 5; ++r)
#pragma unroll
                for (int j = 0; j < 7; ++j) in[r][j] = __ldg(src + r * IMG + j);
#pragma unroll
            for (int i = 0; i < 4; ++i) {
#pragma unroll
                for (int j = 0; j < 7; ++j) {
                    float s = bb;
#pragma unroll
                    for (int di = -1; di <= 1; ++di) {
                        const int ii = i + di;
                        if (ii < 0) continue;
#pragma unroll
                        for (int dj = -1; dj <= 1; ++dj) {
                            const int jj = j + dj;
                            if (jj >= 0 && jj < 7)
                                s += w9[(di + 1) * 3 + (dj + 1)] * in[ii][jj];
                        }
                    }
                    dstp[cc * CSTR + i * 7 + j] = s;
                }
            }
        } else {
            float in[4][7];
#pragma unroll
            for (int r = 0; r < 4; ++r)
#pragma unroll
                for (int j = 0; j < 7; ++j) in[r][j] = __ldg(src + (3 + r) * IMG + j);
#pragma unroll
            for (int i = 4; i < 7; ++i) {
#pragma unroll
                for (int j = 0; j < 7; ++j) {
                    float s = bb;
#pragma unroll
                    for (int di = -1; di <= 1; ++di) {
                        const int ii = i + di;
                        if (ii > 6) continue;
#pragma unroll
                        for (int dj = -1; dj <= 1; ++dj) {
                            const int jj = j + dj;
                            if (jj >= 0 && jj < 7)
                                s += w9[(di + 1) * 3 + (dj + 1)] * in[ii - 3][jj];
                        }
                    }
                    dstp[cc * CSTR + i * 7 + j] = s;
                }
            }
        }
    }
    __syncthreads();

    // ---- phase 2: inverse norms (temperature folded into q side) ----
    if (t < 2 * NPIX) {
        const int part = t / NPIX, p = t % NPIX;
        const float* s = part ? k_s : q_s;
        float acc = 0.f;
#pragma unroll
        for (int c = 0; c < HC; ++c) { const float v = s[c * CSTR + p]; acc += v * v; }
        const float nm = fmaxf(sqrtf(acc), 1e-12f);
        if (part == 0) invq[p] = temperature[h] / nm;
        else           invk[p] = 1.f / nm;
    }
    __syncthreads();

    // ---- phase 3: attn[n][m] = (sum_c k[c][n]*q[c][m]) * invk[n]*invq[m] ----
    if (t < 175) {
        const int n0 = 2 * (t / 7), m0 = 7 * (t % 7);
        const bool hasN1 = (n0 + 1 < NPIX);
        float a0[7], a1[7];
#pragma unroll
        for (int jm = 0; jm < 7; ++jm) { a0[jm] = 0.f; a1[jm] = 0.f; }
#pragma unroll
        for (int c = 0; c < HC; ++c) {
            const float k0 = k_s[c * CSTR + n0];
            const float k1 = hasN1 ? k_s[c * CSTR + n0 + 1] : 0.f;
#pragma unroll
            for (int jm = 0; jm < 7; ++jm) {
                const float qv = q_s[c * CSTR + m0 + jm];
                a0[jm] += k0 * qv;
                a1[jm] += k1 * qv;
            }
        }
        const float ik0 = invk[n0];
#pragma unroll
        for (int jm = 0; jm < 7; ++jm)
            at[n0 * CSTR + m0 + jm] = a0[jm] * ik0 * invq[m0 + jm];
        if (hasN1) {
            const float ik1 = invk[n0 + 1];
#pragma unroll
            for (int jm = 0; jm < 7; ++jm)
                at[(n0 + 1) * CSTR + m0 + jm] = a1[jm] * ik1 * invq[m0 + jm];
        }
    }
    __syncthreads();

    // ---- phase 4: softmax over n per column m (2 threads/col + shfl) ----
    {
        const int m = (t < 98) ? (t >> 1) : 0;   // dummies track col 0
        const int part = t & 1;
        float mx = -1e30f;
        for (int n = part; n < NPIX; n += 2) mx = fmaxf(mx, at[n * CSTR + m]);
        mx = fmaxf(mx, __shfl_xor_sync(0xffffffffu, mx, 1));
        float ev[25];
        float ssum = 0.f;
        int cnt = 0;
        for (int n = part; n < NPIX; n += 2) {
            const float e = __expf(at[n * CSTR + m] - mx);
            ev[cnt++] = e;
            ssum += e;
        }
        ssum += __shfl_xor_sync(0xffffffffu, ssum, 1);
        const float r = 1.f / ssum;
        __syncthreads();   // all reads of at done before stores
        if (t < 98) {
            cnt = 0;
            for (int n = part; n < NPIX; n += 2) at[n * CSTR + m] = ev[cnt++] * r;
        }
    }
    __syncthreads();

    // ---- phase 5: out[c][m] = sum_n v[c][n]*attn[n][m], all 192 threads ----
    for (int u = t; u < HC * 7; u += 192) {      // 224 units: (channel, row-group)
        const int c = u / 7, mg = u % 7;
        const int m0 = 7 * mg;
        float a[7];
#pragma unroll
        for (int jm = 0; jm < 7; ++jm) a[jm] = 0.f;
        for (int n = 0; n < NPIX; ++n) {
            const float v0 = v_s[c * CSTR + n];
#pragma unroll
            for (int jm = 0; jm < 7; ++jm) a[jm] += v0 * at[n * CSTR + m0 + jm];
        }
        float* dst = g_attn + (((size_t)(b * CH + h * HC + c) * IMG) + wh * 7 + mg) * IMG + ww * 7;
#pragma unroll
        for (int jm = 0; jm < 7; ++jm) dst[jm] = a[jm];
    }
}

// ---------------------------------------------------------------------------
extern "C" void kernel_launch(void* const* d_in, const int* in_sizes, int n_in,
                              void* d_out, int out_size)
{
    const float* x      = (const float*)d_in[0];
    const float* w_qkv  = (const float*)d_in[1];
    const float* b_qkv  = (const float*)d_in[2];
    const float* w_dw   = (const float*)d_in[3];
    const float* b_dw   = (const float*)d_in[4];
    const float* w_proj = (const float*)d_in[5];
    const float* b_proj = (const float*)d_in[6];
    const float* temp   = (const float*)d_in[7];
    float* out = (float*)d_out;

    // A: QKV GEMM -> g_qkv
    conv1x1_kernel<OQ, 0><<<dim3(HW / BN, OQ / BM, BATCH), 192>>>(x, w_qkv, b_qkv, nullptr);
    // C: fused dwconv + attention -> g_attn
    attn_kernel<<<dim3(NW, HEADS), 192>>>(w_dw, b_dw, temp);
    // D: proj GEMM -> out
    conv1x1_kernel<CH, 1><<<dim3(HW / BN, CH / BM, BATCH), 192>>>(nullptr, w_proj, b_proj, out);
}

// round 5
// speedup vs baseline: 1.9343x; 1.1547x over previous
#include <cuda_runtime.h>
#include <cstdint>

// ---------------------------------------------------------------------------
// Windowed XCA attention, fp32. B=4, C=192, H=W=224, WS=7 -> nW=4096 windows.
// 3-kernel pipeline:
//   A: QKV dense GEMM (576x192 @ 192x50176 /batch)  -> g_qkv (planar)  [dbuf]
//   C: per (window,head): coalesced load + dwconv3x3(in-place smem) + norms
//      + KtQ + softmax + V*attn                     -> g_attn (planar)
//   D: proj dense GEMM (192x192 @ 192x50176 /batch) -> out (planar)    [dbuf]
// ---------------------------------------------------------------------------

#define BATCH 4
#define CH    192
#define IMG   224
#define HW    50176
#define HEADS 6
#define HC    32
#define NW    4096
#define OQ    576
#define NPIX  49
#define CSTR  50

typedef unsigned long long ull;

__device__ float g_qkv [(size_t)BATCH * OQ * HW];    // 462 MB
__device__ float g_attn[(size_t)BATCH * CH * HW];    // 154 MB

__device__ __forceinline__ ull pack2(float lo, float hi) {
    ull r; asm("mov.b64 %0, {%1, %2};" : "=l"(r) : "f"(lo), "f"(hi)); return r;
}
__device__ __forceinline__ void unpack2(ull v, float& lo, float& hi) {
    asm("mov.b64 {%0, %1}, %2;" : "=f"(lo), "=f"(hi) : "l"(v));
}
__device__ __forceinline__ ull fma2(ull a, ull b, ull c) {
    ull d; asm("fma.rn.f32x2 %0, %1, %2, %3;" : "=l"(d) : "l"(a), "l"(b), "l"(c)); return d;
}

// ---------------------------------------------------------------------------
// A/D: 1x1 conv dense GEMM, double-buffered smem + register prefetch.
// Block tile 96(M) x 128(N), BK=16, 192 threads, thread tile 8x8 (f32x2).
// MODE 0: in = param x, out = g_qkv.  MODE 1: in = g_attn, out = param.
// ---------------------------------------------------------------------------
#define BM 96
#define BN 128
#define BK 16
#define KITERS (CH / BK)   // 12

template<int MT, int MODE>
__global__ __launch_bounds__(192, 2)
void conv1x1_kernel(const float* __restrict__ in_p,
                    const float* __restrict__ w,
                    const float* __restrict__ bias,
                    float* __restrict__ out_p)
{
    __shared__ float a_s[2][BK][BM + 4];   // transposed weights
    __shared__ float b_s[2][BK][BN];       // input pixels

    const float* in = (MODE == 0) ? in_p : (const float*)g_attn;
    float* out      = (MODE == 0) ? (float*)g_qkv : out_p;

    const int t  = threadIdx.x;
    const int n0 = blockIdx.x * BN;
    const int m0 = blockIdx.y * BM;
    const int b  = blockIdx.z;

    const float* inb = in + (size_t)b * CH * HW + n0;
    const float* wb  = w + m0 * CH;
    float* outb = out + ((size_t)b * MT + m0) * HW + n0;

    const int tx = t & 15;       // 16 N-groups of 8 pixels
    const int ty = t >> 4;       // 12 M-groups of 8 outputs
    const int pn = tx * 8;
    const int om = ty * 8;

    // prefetch mapping
    const int bu0 = t, bu1 = t + 192, bu2 = t + 384;       // b tile: 512 float4
    const int au0 = t, au1 = t + 192;                      // a tile: 384 float4
    const int b_row0 = bu0 >> 5, b_col0 = (bu0 & 31) * 4;
    const int b_row1 = bu1 >> 5, b_col1 = (bu1 & 31) * 4;
    const int b_row2 = bu2 >> 5, b_col2 = (bu2 & 31) * 4;
    const int a_o0 = au0 >> 2, a_q0 = (au0 & 3) * 4;
    const int a_o1 = au1 >> 2, a_q1 = (au1 & 3) * 4;

    float4 pb0, pb1, pb2, pa0, pa1;

    // prologue: load tile 0
    {
        const int kb = 0;
        pb0 = *(const float4*)(inb + (size_t)(kb + b_row0) * HW + b_col0);
        pb1 = *(const float4*)(inb + (size_t)(kb + b_row1) * HW + b_col1);
        if (t < 128) pb2 = *(const float4*)(inb + (size_t)(kb + b_row2) * HW + b_col2);
        pa0 = *(const float4*)(wb + a_o0 * CH + kb + a_q0);
        pa1 = *(const float4*)(wb + a_o1 * CH + kb + a_q1);
        *(float4*)&b_s[0][b_row0][b_col0] = pb0;
        *(float4*)&b_s[0][b_row1][b_col1] = pb1;
        if (t < 128) *(float4*)&b_s[0][b_row2][b_col2] = pb2;
        a_s[0][a_q0 + 0][a_o0] = pa0.x; a_s[0][a_q0 + 1][a_o0] = pa0.y;
        a_s[0][a_q0 + 2][a_o0] = pa0.z; a_s[0][a_q0 + 3][a_o0] = pa0.w;
        a_s[0][a_q1 + 0][a_o1] = pa1.x; a_s[0][a_q1 + 1][a_o1] = pa1.y;
        a_s[0][a_q1 + 2][a_o1] = pa1.z; a_s[0][a_q1 + 3][a_o1] = pa1.w;
    }
    __syncthreads();

    ull acc[8][4];
#pragma unroll
    for (int i = 0; i < 8; ++i)
#pragma unroll
        for (int p = 0; p < 4; ++p) acc[i][p] = 0ULL;

    for (int it = 0; it < KITERS; ++it) {
        const int cur = it & 1;
        // issue global loads for next tile (latency hidden under compute)
        if (it < KITERS - 1) {
            const int kb = (it + 1) * BK;
            pb0 = *(const float4*)(inb + (size_t)(kb + b_row0) * HW + b_col0);
            pb1 = *(const float4*)(inb + (size_t)(kb + b_row1) * HW + b_col1);
            if (t < 128) pb2 = *(const float4*)(inb + (size_t)(kb + b_row2) * HW + b_col2);
            pa0 = *(const float4*)(wb + a_o0 * CH + kb + a_q0);
            pa1 = *(const float4*)(wb + a_o1 * CH + kb + a_q1);
        }
        // compute current tile
#pragma unroll
        for (int kk = 0; kk < BK; ++kk) {
            const float4 wa = *(const float4*)&a_s[cur][kk][om];
            const float4 wc = *(const float4*)&a_s[cur][kk][om + 4];
            const float4 xa = *(const float4*)&b_s[cur][kk][pn];
            const float4 xb = *(const float4*)&b_s[cur][kk][pn + 4];
            ull xp[4];
            xp[0] = pack2(xa.x, xa.y); xp[1] = pack2(xa.z, xa.w);
            xp[2] = pack2(xb.x, xb.y); xp[3] = pack2(xb.z, xb.w);
            const float av[8] = {wa.x, wa.y, wa.z, wa.w, wc.x, wc.y, wc.z, wc.w};
#pragma unroll
            for (int i = 0; i < 8; ++i) {
                const ull wp = pack2(av[i], av[i]);
#pragma unroll
                for (int p = 0; p < 4; ++p) acc[i][p] = fma2(wp, xp[p], acc[i][p]);
            }
        }
        // store prefetched tile to the other buffer
        if (it < KITERS - 1) {
            const int nb = cur ^ 1;
            *(float4*)&b_s[nb][b_row0][b_col0] = pb0;
            *(float4*)&b_s[nb][b_row1][b_col1] = pb1;
            if (t < 128) *(float4*)&b_s[nb][b_row2][b_col2] = pb2;
            a_s[nb][a_q0 + 0][a_o0] = pa0.x; a_s[nb][a_q0 + 1][a_o0] = pa0.y;
            a_s[nb][a_q0 + 2][a_o0] = pa0.z; a_s[nb][a_q0 + 3][a_o0] = pa0.w;
            a_s[nb][a_q1 + 0][a_o1] = pa1.x; a_s[nb][a_q1 + 1][a_o1] = pa1.y;
            a_s[nb][a_q1 + 2][a_o1] = pa1.z; a_s[nb][a_q1 + 3][a_o1] = pa1.w;
            __syncthreads();
        }
    }

#pragma unroll
    for (int i = 0; i < 8; ++i) {
        const int o = om + i;
        const float bb = bias[m0 + o];
        float r0, r1, r2, r3;
        unpack2(acc[i][0], r0, r1); unpack2(acc[i][1], r2, r3);
        *(float4*)(outb + (size_t)o * HW + pn) =
            make_float4(r0 + bb, r1 + bb, r2 + bb, r3 + bb);
        unpack2(acc[i][2], r0, r1); unpack2(acc[i][3], r2, r3);
        *(float4*)(outb + (size_t)o * HW + pn + 4) =
            make_float4(r0 + bb, r1 + bb, r2 + bb, r3 + bb);
    }
}

// ---------------------------------------------------------------------------
// C: attention per (window, head). grid (NW, HEADS), 192 thr, ~30 KB smem.
// phase 0: coalesced cooperative load of 96ch x 49px slab into q/k/v smem
// phase 1: dwconv3x3 in place (inputs staged to registers, one sync)
// phase 2: norms, 3: KtQ*scales, 4: softmax(n), 5: V*attn -> planar g_attn
// ---------------------------------------------------------------------------
__global__ __launch_bounds__(192)
void attn_kernel(const float* __restrict__ w_dw,
                 const float* __restrict__ b_dw,
                 const float* __restrict__ temperature)
{
    __shared__ float q_s[HC * CSTR];
    __shared__ float k_s[HC * CSTR];
    __shared__ float v_s[HC * CSTR];
    __shared__ float at [NPIX * CSTR];
    __shared__ float invq[NPIX], invk[NPIX];

    const int win = blockIdx.x;
    const int h   = blockIdx.y;
    const int t   = threadIdx.x;
    const int b  = win >> 10;
    const int wh = (win >> 5) & 31;
    const int ww = win & 31;

    // ---- phase 0: coalesced load (consecutive threads = consecutive pixels)
    {
        const size_t gbase = (size_t)b * OQ * HW + (size_t)(wh * 7) * IMG + ww * 7;
#pragma unroll
        for (int it = 0; it < 25; ++it) {
            const int u = t + it * 192;
            if (u < 96 * NPIX) {
                const int c = u / NPIX, p = u % NPIX;
                const int sel = c >> 5, cc = c & 31;
                const int ch = sel * CH + h * HC + cc;
                const float v = __ldg(&g_qkv[gbase + (size_t)ch * HW + (p / 7) * IMG + p % 7]);
                float* dstp = (sel == 0) ? q_s : (sel == 1) ? k_s : v_s;
                dstp[cc * CSTR + p] = v;
            }
        }
    }
    __syncthreads();

    // ---- phase 1: dwconv 3x3 in place (window zero-padded) ----
    {
        const int c    = t >> 1;          // 0..95
        const int half = t & 1;
        const int sel  = c >> 5;          // 0=q 1=k 2=v
        const int cc   = c & 31;
        const int ch   = sel * CH + h * HC + cc;
        float* dstp = (sel == 0) ? q_s : (sel == 1) ? k_s : v_s;
        float* row0 = dstp + cc * CSTR;

        float w9[9];
#pragma unroll
        for (int k = 0; k < 9; ++k) w9[k] = w_dw[ch * 9 + k];
        const float bb = b_dw[ch];

        // stage needed input rows to registers (half 0: rows 0-4, half 1: rows 3-6)
        float in[5][7];
        const int r0 = half ? 3 : 0;
        const int nr = half ? 4 : 5;
        for (int r = 0; r < nr; ++r)
#pragma unroll
            for (int j = 0; j < 7; ++j) in[r][j] = row0[(r0 + r) * 7 + j];
        __syncthreads();   // all reads done before in-place writes

        if (!half) {
#pragma unroll
            for (int i = 0; i < 4; ++i) {
#pragma unroll
                for (int j = 0; j < 7; ++j) {
                    float s = bb;
#pragma unroll
                    for (int di = -1; di <= 1; ++di) {
                        const int ii = i + di;
                        if (ii < 0) continue;
#pragma unroll
                        for (int dj = -1; dj <= 1; ++dj) {
                            const int jj = j + dj;
                            if (jj >= 0 && jj < 7)
                                s += w9[(di + 1) * 3 + (dj + 1)] * in[ii][jj];
                        }
                    }
                    row0[i * 7 + j] = s;
                }
            }
        } else {
#pragma unroll
            for (int i = 4; i < 7; ++i) {
#pragma unroll
                for (int j = 0; j < 7; ++j) {
                    float s = bb;
#pragma unroll
                    for (int di = -1; di <= 1; ++di) {
                        const int ii = i + di;
                        if (ii > 6) continue;
#pragma unroll
                        for (int dj = -1; dj <= 1; ++dj) {
                            const int jj = j + dj;
                            if (jj >= 0 && jj < 7)
                                s += w9[(di + 1) * 3 + (dj + 1)] * in[ii - 3][jj];
                        }
                    }
                    row0[i * 7 + j] = s;
                }
            }
        }
    }
    __syncthreads();

    // ---- phase 2: inverse norms (temperature folded into q side) ----
    if (t < 2 * NPIX) {
        const int part = t / NPIX, p = t % NPIX;
        const float* s = part ? k_s : q_s;
        float acc = 0.f;
#pragma unroll
        for (int c = 0; c < HC; ++c) { const float v = s[c * CSTR + p]; acc += v * v; }
        const float nm = fmaxf(sqrtf(acc), 1e-12f);
        if (part == 0) invq[p] = temperature[h] / nm;
        else           invk[p] = 1.f / nm;
    }
    __syncthreads();

    // ---- phase 3: attn[n][m] = (sum_c k[c][n]*q[c][m]) * invk[n]*invq[m] ----
    if (t < 175) {
        const int n0 = 2 * (t / 7), m0 = 7 * (t % 7);
        const bool hasN1 = (n0 + 1 < NPIX);
        float a0[7], a1[7];
#pragma unroll
        for (int jm = 0; jm < 7; ++jm) { a0[jm] = 0.f; a1[jm] = 0.f; }
#pragma unroll
        for (int c = 0; c < HC; ++c) {
            const float k0 = k_s[c * CSTR + n0];
            const float k1 = hasN1 ? k_s[c * CSTR + n0 + 1] : 0.f;
#pragma unroll
            for (int jm = 0; jm < 7; ++jm) {
                const float qv = q_s[c * CSTR + m0 + jm];
                a0[jm] += k0 * qv;
                a1[jm] += k1 * qv;
            }
        }
        const float ik0 = invk[n0];
#pragma unroll
        for (int jm = 0; jm < 7; ++jm)
            at[n0 * CSTR + m0 + jm] = a0[jm] * ik0 * invq[m0 + jm];
        if (hasN1) {
            const float ik1 = invk[n0 + 1];
#pragma unroll
            for (int jm = 0; jm < 7; ++jm)
                at[(n0 + 1) * CSTR + m0 + jm] = a1[jm] * ik1 * invq[m0 + jm];
        }
    }
    __syncthreads();

    // ---- phase 4: softmax over n per column m (2 threads/col + shfl) ----
    {
        const int m = (t < 98) ? (t >> 1) : 0;   // dummies track col 0
        const int part = t & 1;
        float mx = -1e30f;
        for (int n = part; n < NPIX; n += 2) mx = fmaxf(mx, at[n * CSTR + m]);
        mx = fmaxf(mx, __shfl_xor_sync(0xffffffffu, mx, 1));
        float ev[25];
        float ssum = 0.f;
        int cnt = 0;
        for (int n = part; n < NPIX; n += 2) {
            const float e = __expf(at[n * CSTR + m] - mx);
            ev[cnt++] = e;
            ssum += e;
        }
        ssum += __shfl_xor_sync(0xffffffffu, ssum, 1);
        const float r = 1.f / ssum;
        __syncthreads();   // all reads of at done before stores
        if (t < 98) {
            cnt = 0;
            for (int n = part; n < NPIX; n += 2) at[n * CSTR + m] = ev[cnt++] * r;
        }
    }
    __syncthreads();

    // ---- phase 5: out[c][m] = sum_n v[c][n]*attn[n][m], all 192 threads ----
    for (int u = t; u < HC * 7; u += 192) {      // 224 units: (channel, row-group)
        const int c = u / 7, mg = u % 7;
        const int m0 = 7 * mg;
        float a[7];
#pragma unroll
        for (int jm = 0; jm < 7; ++jm) a[jm] = 0.f;
        for (int n = 0; n < NPIX; ++n) {
            const float v0 = v_s[c * CSTR + n];
#pragma unroll
            for (int jm = 0; jm < 7; ++jm) a[jm] += v0 * at[n * CSTR + m0 + jm];
        }
        float* dst = g_attn + (((size_t)(b * CH + h * HC + c) * IMG) + wh * 7 + mg) * IMG + ww * 7;
#pragma unroll
        for (int jm = 0; jm < 7; ++jm) dst[jm] = a[jm];
    }
}

// ---------------------------------------------------------------------------
extern "C" void kernel_launch(void* const* d_in, const int* in_sizes, int n_in,
                              void* d_out, int out_size)
{
    const float* x      = (const float*)d_in[0];
    const float* w_qkv  = (const float*)d_in[1];
    const float* b_qkv  = (const float*)d_in[2];
    const float* w_dw   = (const float*)d_in[3];
    const float* b_dw   = (const float*)d_in[4];
    const float* w_proj = (const float*)d_in[5];
    const float* b_proj = (const float*)d_in[6];
    const float* temp   = (const float*)d_in[7];
    float* out = (float*)d_out;

    // A: QKV GEMM -> g_qkv
    conv1x1_kernel<OQ, 0><<<dim3(HW / BN, OQ / BM, BATCH), 192>>>(x, w_qkv, b_qkv, nullptr);
    // C: fused dwconv + attention -> g_attn
    attn_kernel<<<dim3(NW, HEADS), 192>>>(w_dw, b_dw, temp);
    // D: proj GEMM -> out
    conv1x1_kernel<CH, 1><<<dim3(HW / BN, CH / BM, BATCH), 192>>>(nullptr, w_proj, b_proj, out);
}